// round 3
// baseline (speedup 1.0000x reference)
#include <cuda_runtime.h>

// y[b, i] = input[b, i] * diag(weight)[i] + bias[i]
// B = 8192, N = 4096, fp32.

#define N_COLS 4096
#define N4 (N_COLS / 4)          // 1024 float4 columns

// Scratch for the gathered diagonal (allocation-free rule: __device__ global).
__device__ float g_diag[N_COLS];

__global__ void extract_diag_kernel(const float* __restrict__ weight, int n) {
    int i = blockIdx.x * blockDim.x + threadIdx.x;
    if (i < n) {
        // weight is [n, n] row-major; diagonal element at i*(n+1)
        g_diag[i] = weight[(size_t)i * (size_t)(n + 1)];
    }
}

__global__ void scale_bias_kernel(const float4* __restrict__ in,
                                  const float4* __restrict__ bias4,
                                  float4* __restrict__ out,
                                  int total4) {
    const float4* __restrict__ d4 = reinterpret_cast<const float4*>(g_diag);

    int stride = gridDim.x * blockDim.x;
    // Grid-stride loop, 2 independent float4s per iteration for MLP.
    for (int idx = blockIdx.x * blockDim.x + threadIdx.x; idx < total4; idx += 2 * stride) {
        int idx2 = idx + stride;
        bool has2 = idx2 < total4;

        // Issue both input loads up front (independent -> MLP=2).
        float4 x0 = in[idx];
        float4 x1 = has2 ? in[idx2] : make_float4(0.f, 0.f, 0.f, 0.f);

        int c0 = idx & (N4 - 1);   // column in float4 units (N4 power of two)
        float4 d0 = d4[c0];        // 16 KB table, L1-resident
        float4 b0 = bias4[c0];     // 16 KB table, L1-resident

        float4 y0;
        y0.x = fmaf(x0.x, d0.x, b0.x);
        y0.y = fmaf(x0.y, d0.y, b0.y);
        y0.z = fmaf(x0.z, d0.z, b0.z);
        y0.w = fmaf(x0.w, d0.w, b0.w);
        out[idx] = y0;

        if (has2) {
            int c1 = idx2 & (N4 - 1);
            float4 d1 = d4[c1];
            float4 b1 = bias4[c1];
            float4 y1;
            y1.x = fmaf(x1.x, d1.x, b1.x);
            y1.y = fmaf(x1.y, d1.y, b1.y);
            y1.z = fmaf(x1.z, d1.z, b1.z);
            y1.w = fmaf(x1.w, d1.w, b1.w);
            out[idx2] = y1;
        }
    }
}

extern "C" void kernel_launch(void* const* d_in, const int* in_sizes, int n_in,
                              void* d_out, int out_size) {
    const float* input  = (const float*)d_in[0];   // [B, N]
    const float* weight = (const float*)d_in[1];   // [N, N]
    const float* bias   = (const float*)d_in[2];   // [N]

    float* out = (float*)d_out;

    const int n = N_COLS;
    const int total4 = out_size / 4;  // B*N/4 float4 elements

    // 1) gather diagonal into g_diag
    extract_diag_kernel<<<(n + 255) / 256, 256>>>(weight, n);

    // 2) streaming scale + bias, float4-vectorized, 2 float4 per thread
    const int threads = 256;
    int blocks = (total4 + 2 * threads - 1) / (2 * threads);
    scale_bias_kernel<<<blocks, threads>>>(
        reinterpret_cast<const float4*>(input),
        reinterpret_cast<const float4*>(bias),
        reinterpret_cast<float4*>(out),
        total4);
}